// round 2
// baseline (speedup 1.0000x reference)
#include <cuda_runtime.h>
#include <cuda_bf16.h>
#include <cstdint>

// ======================= problem constants =======================
#define NB   3
#define BSZ  256
#define NF   8192
#define DDIM 2048
#define TEMP_INV 20.0f
#define NEPS 1e-12f

// ======================= static device scratch =======================
__device__ __align__(256) __nv_bfloat16 g_xn[NB * BSZ * DDIM];
__device__ __align__(256) __nv_bfloat16 g_fb[(size_t)NB * NF * DDIM];
__device__ float g_x2[NB * BSZ];
__device__ float g_f2[NB * NF];
__device__ __align__(256) float g_dot[(size_t)NB * BSZ * NF];
__device__ float g_rowloss[NB * BSZ];

// ======================= helpers =======================
__device__ __forceinline__ uint32_t smem_u32(const void* p) {
    uint32_t a;
    asm("{ .reg .u64 t; cvta.to.shared.u64 t, %1; cvt.u32.u64 %0, t; }" : "=r"(a) : "l"(p));
    return a;
}

__device__ __forceinline__ void cp16(uint32_t saddr, const void* g) {
    asm volatile("cp.async.cg.shared.global [%0], [%1], 16;" :: "r"(saddr), "l"(g) : "memory");
}
#define CP_COMMIT() asm volatile("cp.async.commit_group;" ::: "memory")
#define CP_WAIT0()  asm volatile("cp.async.wait_group 0;" ::: "memory")

__device__ __forceinline__ void ldsm_x4(uint32_t* r, uint32_t addr) {
    asm volatile("ldmatrix.sync.aligned.m8n8.x4.shared.b16 {%0,%1,%2,%3}, [%4];"
                 : "=r"(r[0]), "=r"(r[1]), "=r"(r[2]), "=r"(r[3]) : "r"(addr));
}

__device__ __forceinline__ void mma16816(float* c, const uint32_t* a, uint32_t b0, uint32_t b1) {
    asm volatile(
        "mma.sync.aligned.m16n8k16.row.col.f32.bf16.bf16.f32 "
        "{%0,%1,%2,%3}, {%4,%5,%6,%7}, {%8,%9}, {%0,%1,%2,%3};"
        : "+f"(c[0]), "+f"(c[1]), "+f"(c[2]), "+f"(c[3])
        : "r"(a[0]), "r"(a[1]), "r"(a[2]), "r"(a[3]), "r"(b0), "r"(b1));
}

// block reduce (blockDim.x == 256); result valid for tid 0
__device__ __forceinline__ float blockReduceSum(float v) {
    __shared__ float red[8];
    const unsigned m = 0xffffffffu;
    v += __shfl_xor_sync(m, v, 16);
    v += __shfl_xor_sync(m, v, 8);
    v += __shfl_xor_sync(m, v, 4);
    v += __shfl_xor_sync(m, v, 2);
    v += __shfl_xor_sync(m, v, 1);
    __syncthreads();
    if ((threadIdx.x & 31) == 0) red[threadIdx.x >> 5] = v;
    __syncthreads();
    if (threadIdx.x < 8) {
        v = red[threadIdx.x];
        v += __shfl_xor_sync(0xffu, v, 4);
        v += __shfl_xor_sync(0xffu, v, 2);
        v += __shfl_xor_sync(0xffu, v, 1);
    }
    return v;
}

// ======================= kernel 1: normalize / convert / sumsq =======================
__global__ void __launch_bounds__(256) prep_kernel(
    const float* __restrict__ x0, const float* __restrict__ x1, const float* __restrict__ x2,
    const float* __restrict__ f0, const float* __restrict__ f1, const float* __restrict__ f2)
{
    const int r = blockIdx.x;
    const int tid = threadIdx.x;
    const float* src;
    __nv_bfloat16* dst;
    bool isx;
    int fr = 0;
    if (r < NB * BSZ) {
        int br = r / BSZ;
        int b = r - br * BSZ;
        const float* base = (br == 0) ? x0 : (br == 1) ? x1 : x2;
        src = base + (size_t)b * DDIM;
        dst = g_xn + (size_t)r * DDIM;
        isx = true;
    } else {
        fr = r - NB * BSZ;
        int br = fr >> 13;
        int n = fr & (NF - 1);
        const float* base = (br == 0) ? f0 : (br == 1) ? f1 : f2;
        src = base + (size_t)n * DDIM;
        dst = g_fb + (size_t)fr * DDIM;
        isx = false;
    }

    float v[8];
    float ss = 0.0f;
#pragma unroll
    for (int i = 0; i < 8; i++) {
        v[i] = src[tid + i * 256];
        ss += v[i] * v[i];
    }
    ss = blockReduceSum(ss);
    __shared__ float s_bcast;
    if (tid == 0) s_bcast = ss;
    __syncthreads();
    ss = s_bcast;

    float scale = 1.0f;
    if (isx) {
        float nrm = sqrtf(ss);
        scale = 1.0f / fmaxf(nrm, NEPS);
        if (tid == 0) g_x2[r] = ss * scale * scale;
    } else {
        if (tid == 0) g_f2[fr] = ss;
    }
#pragma unroll
    for (int i = 0; i < 8; i++) dst[tid + i * 256] = __float2bfloat16(v[i] * scale);
}

// ======================= kernel 2: mma.sync bf16 GEMM =======================
#define BM 128
#define BN 128
#define BK 32
#define NK (DDIM / BK)
#define STG_A (BM * BK)
#define STG_B (BN * BK)

__global__ void __launch_bounds__(256) gemm_kernel() {
    __shared__ __align__(128) __nv_bfloat16 sA[2][STG_A];
    __shared__ __align__(128) __nv_bfloat16 sB[2][STG_B];

    const int tid = threadIdx.x;
    const int wid = tid >> 5;
    const int lid = tid & 31;
    const int br = blockIdx.z;
    const int m0 = blockIdx.y * BM;
    const int n0 = blockIdx.x * BN;
    const int warp_m = wid & 1;
    const int warp_n = wid >> 1;

    const __nv_bfloat16* __restrict__ Ab = g_xn + (size_t)(br * BSZ + m0) * DDIM;
    const __nv_bfloat16* __restrict__ Bb = g_fb + ((size_t)br * NF + n0) * DDIM;

    const uint32_t sAu = smem_u32(sA);
    const uint32_t sBu = smem_u32(sB);

    // cp.async mapping: 512 16B-chunks per tile, 2 per thread per operand
    const int c0 = tid, c1 = tid + 256;
    const int r0 = c0 >> 2, h0 = c0 & 3;
    const int r1 = c1 >> 2, h1 = c1 & 3;
    const uint32_t so0 = (uint32_t)(r0 * 64 + ((h0 ^ ((r0 >> 1) & 3)) << 4));
    const uint32_t so1 = (uint32_t)(r1 * 64 + ((h1 ^ ((r1 >> 1) & 3)) << 4));
    const __nv_bfloat16* gA0 = Ab + (size_t)r0 * DDIM + h0 * 8;
    const __nv_bfloat16* gA1 = Ab + (size_t)r1 * DDIM + h1 * 8;
    const __nv_bfloat16* gB0 = Bb + (size_t)r0 * DDIM + h0 * 8;
    const __nv_bfloat16* gB1 = Bb + (size_t)r1 * DDIM + h1 * 8;

    // ldmatrix fragment address bases
    const int rowA = warp_m * 64 + (lid & 15);
    const uint32_t swA = (uint32_t)((rowA >> 1) & 3);
    const int rowB0 = warp_n * 32 + (lid & 15);
    const int rowB1 = rowB0 + 16;
    const uint32_t swB0 = (uint32_t)((rowB0 >> 1) & 3);
    const uint32_t swB1 = (uint32_t)((rowB1 >> 1) & 3);
    const uint32_t hi = (uint32_t)(lid >> 4);

    float acc[4][4][4];
#pragma unroll
    for (int i = 0; i < 4; i++)
#pragma unroll
        for (int j = 0; j < 4; j++)
#pragma unroll
            for (int k = 0; k < 4; k++) acc[i][j][k] = 0.0f;

    // prologue: stage 0
    cp16(sAu + so0, gA0);
    cp16(sAu + so1, gA1);
    cp16(sBu + so0, gB0);
    cp16(sBu + so1, gB1);
    CP_COMMIT();

    for (int kt = 0; kt < NK; kt++) {
        CP_WAIT0();
        __syncthreads();
        if (kt + 1 < NK) {
            const int koff = (kt + 1) * BK;
            const uint32_t bo = ((kt + 1) & 1) ? (uint32_t)(STG_A * 2) : 0u;
            cp16(sAu + bo + so0, gA0 + koff);
            cp16(sAu + bo + so1, gA1 + koff);
            cp16(sBu + bo + so0, gB0 + koff);
            cp16(sBu + bo + so1, gB1 + koff);
            CP_COMMIT();
        }
        const uint32_t abase = sAu + ((kt & 1) ? (uint32_t)(STG_A * 2) : 0u);
        const uint32_t bbase = sBu + ((kt & 1) ? (uint32_t)(STG_B * 2) : 0u);
#pragma unroll
        for (int ks = 0; ks < 2; ks++) {
            const uint32_t ch = (uint32_t)(ks * 2) + hi;
            uint32_t a[4][4];
#pragma unroll
            for (int mt = 0; mt < 4; mt++)
                ldsm_x4(a[mt], abase + (uint32_t)((rowA + mt * 16) * 64) + ((ch ^ swA) << 4));
            uint32_t b[2][4];
            ldsm_x4(b[0], bbase + (uint32_t)(rowB0 * 64) + ((ch ^ swB0) << 4));
            ldsm_x4(b[1], bbase + (uint32_t)(rowB1 * 64) + ((ch ^ swB1) << 4));
#pragma unroll
            for (int mt = 0; mt < 4; mt++)
#pragma unroll
                for (int nt = 0; nt < 4; nt++)
                    mma16816(acc[mt][nt], a[mt], b[nt >> 1][nt & 1], b[nt >> 1][2 + (nt & 1)]);
        }
        __syncthreads();
    }

    // epilogue
    float* Crow = g_dot + (size_t)(br * BSZ + m0 + warp_m * 64) * NF + n0 + warp_n * 32;
    const int rr = lid >> 2;
    const int cc = (lid & 3) * 2;
#pragma unroll
    for (int mt = 0; mt < 4; mt++)
#pragma unroll
        for (int nt = 0; nt < 4; nt++) {
            float2 v0 = make_float2(acc[mt][nt][0], acc[mt][nt][1]);
            float2 v1 = make_float2(acc[mt][nt][2], acc[mt][nt][3]);
            *(float2*)&Crow[(size_t)(mt * 16 + rr) * NF + nt * 8 + cc] = v0;
            *(float2*)&Crow[(size_t)(mt * 16 + rr + 8) * NF + nt * 8 + cc] = v1;
        }
}

// ======================= kernel 3: per-row loss =======================
__global__ void __launch_bounds__(256) rowloss_kernel(const int* __restrict__ targets) {
    const int r = blockIdx.x;
    const int br = r >> 8;
    const int b = r & 255;
    const float* drow = g_dot + (size_t)r * NF;
    const float* f2 = g_f2 + br * NF;
    const float x2 = g_x2[r];
    const int tid = threadIdx.x;

    __shared__ float sm[NF];

    float s1 = 0.0f, s2 = 0.0f;
#pragma unroll 4
    for (int i = 0; i < NF / 256; i++) {
        int n = tid + i * 256;
        float dot = drow[n];
        s1 += expf(dot * TEMP_INV);
        float d2 = x2 + f2[n] - 2.0f * dot;
        float d = sqrtf(fmaxf(d2, 0.0f));
        float ed = expf(d);
        s2 += ed;
        sm[n] = ed;
    }
    s1 = blockReduceSum(s1);
    __shared__ float sS1;
    if (tid == 0) sS1 = s1;
    s2 = blockReduceSum(s2);
    __shared__ float sS2;
    if (tid == 0) sS2 = s2;
    __syncthreads();
    const float inv2 = 1.0f / sS2;

    float s3 = 0.0f;
#pragma unroll 4
    for (int i = 0; i < NF / 256; i++) {
        int n = tid + i * 256;
        s3 += expf(sm[n] * inv2);
    }
    s3 = blockReduceSum(s3);

    if (tid == 0) {
        int t = targets[b];
        float dott = drow[t];
        float d2t = x2 + f2[t] - 2.0f * dott;
        float dt = sqrtf(fmaxf(d2t, 0.0f));
        float loss1 = logf(sS1) - dott * TEMP_INV;
        float loss2 = logf(s3) - expf(dt) * inv2;
        g_rowloss[r] = loss1 + loss2;
    }
}

// ======================= kernel 4: final reduce =======================
__global__ void __launch_bounds__(256) final_kernel(float* __restrict__ out) {
    const int tid = threadIdx.x;
    float v = g_rowloss[tid] + g_rowloss[tid + 256] + g_rowloss[tid + 512];
    v = blockReduceSum(v);
    if (tid == 0) out[0] = v * (0.5f / 256.0f);
}

// ======================= launch =======================
extern "C" void kernel_launch(void* const* d_in, const int* in_sizes, int n_in,
                              void* d_out, int out_size) {
    const float* inputs      = (const float*)d_in[0];
    const float* inputs_up   = (const float*)d_in[1];
    const float* inputs_down = (const float*)d_in[2];
    const int*   targets     = (const int*)d_in[3];
    const float* features      = (const float*)d_in[5];
    const float* features_up   = (const float*)d_in[6];
    const float* features_down = (const float*)d_in[7];
    float* out = (float*)d_out;

    prep_kernel<<<NB * BSZ + NB * NF, 256>>>(inputs, inputs_up, inputs_down,
                                             features, features_up, features_down);
    gemm_kernel<<<dim3(NF / BN, BSZ / BM, NB), 256>>>();
    rowloss_kernel<<<NB * BSZ, 256>>>(targets);
    final_kernel<<<1, 256>>>(out);
}

// round 3
// speedup vs baseline: 1.0374x; 1.0374x over previous
#include <cuda_runtime.h>
#include <cuda_bf16.h>
#include <cstdint>

// ======================= problem constants =======================
#define NB   3
#define BSZ  256
#define NF   8192
#define DDIM 2048
#define TEMP_INV 20.0f
#define NEPS 1e-12f

// GEMM tiling
#define BM 256
#define BN 64
#define BK 32
#define NK (DDIM / BK)

// ======================= static device scratch =======================
__device__ __align__(256) __nv_bfloat16 g_xn[NB * BSZ * DDIM];
__device__ float g_x2[NB * BSZ];
__device__ float g_f2[NB * NF];
__device__ __align__(256) float g_dot[(size_t)NB * BSZ * NF];
__device__ float g_rowloss[NB * BSZ];

// ======================= helpers =======================
__device__ __forceinline__ uint32_t smem_u32(const void* p) {
    uint32_t a;
    asm("{ .reg .u64 t; cvta.to.shared.u64 t, %1; cvt.u32.u64 %0, t; }" : "=r"(a) : "l"(p));
    return a;
}

__device__ __forceinline__ void cp16(uint32_t saddr, const void* g) {
    asm volatile("cp.async.cg.shared.global [%0], [%1], 16;" :: "r"(saddr), "l"(g) : "memory");
}
#define CP_COMMIT() asm volatile("cp.async.commit_group;" ::: "memory")
#define CP_WAIT0()  asm volatile("cp.async.wait_group 0;" ::: "memory")

__device__ __forceinline__ void ldsm_x4(uint32_t* r, uint32_t addr) {
    asm volatile("ldmatrix.sync.aligned.m8n8.x4.shared.b16 {%0,%1,%2,%3}, [%4];"
                 : "=r"(r[0]), "=r"(r[1]), "=r"(r[2]), "=r"(r[3]) : "r"(addr));
}

__device__ __forceinline__ void mma16816(float* c, const uint32_t* a, uint32_t b0, uint32_t b1) {
    asm volatile(
        "mma.sync.aligned.m16n8k16.row.col.f32.bf16.bf16.f32 "
        "{%0,%1,%2,%3}, {%4,%5,%6,%7}, {%8,%9}, {%0,%1,%2,%3};"
        : "+f"(c[0]), "+f"(c[1]), "+f"(c[2]), "+f"(c[3])
        : "r"(a[0]), "r"(a[1]), "r"(a[2]), "r"(a[3]), "r"(b0), "r"(b1));
}

__device__ __forceinline__ void sts128u(uint32_t addr, uint32_t x, uint32_t y, uint32_t z, uint32_t w) {
    asm volatile("st.shared.v4.b32 [%0], {%1, %2, %3, %4};"
                 :: "r"(addr), "r"(x), "r"(y), "r"(z), "r"(w) : "memory");
}

// block reduce (blockDim.x == 256); result valid for tid 0
__device__ __forceinline__ float blockReduceSum(float v) {
    __shared__ float red[8];
    const unsigned m = 0xffffffffu;
    v += __shfl_xor_sync(m, v, 16);
    v += __shfl_xor_sync(m, v, 8);
    v += __shfl_xor_sync(m, v, 4);
    v += __shfl_xor_sync(m, v, 2);
    v += __shfl_xor_sync(m, v, 1);
    __syncthreads();
    if ((threadIdx.x & 31) == 0) red[threadIdx.x >> 5] = v;
    __syncthreads();
    if (threadIdx.x < 8) {
        v = red[threadIdx.x];
        v += __shfl_xor_sync(0xffu, v, 4);
        v += __shfl_xor_sync(0xffu, v, 2);
        v += __shfl_xor_sync(0xffu, v, 1);
    }
    return v;
}

// ======================= kernel 1: normalize x rows -> bf16 =======================
// grid: NB*BSZ blocks, 256 threads
__global__ void __launch_bounds__(256) prep_x_kernel(
    const float* __restrict__ x0, const float* __restrict__ x1, const float* __restrict__ x2)
{
    const int r = blockIdx.x;              // 0..767
    const int tid = threadIdx.x;
    const int br = r >> 8;
    const int b = r & 255;
    const float* base = (br == 0) ? x0 : (br == 1) ? x1 : x2;
    const float* src = base + (size_t)b * DDIM;
    __nv_bfloat16* dst = g_xn + (size_t)r * DDIM;

    float v[8];
    float ss = 0.0f;
#pragma unroll
    for (int i = 0; i < 8; i++) {
        v[i] = src[tid + i * 256];
        ss += v[i] * v[i];
    }
    ss = blockReduceSum(ss);
    __shared__ float s_bcast;
    if (tid == 0) s_bcast = ss;
    __syncthreads();
    ss = s_bcast;

    float nrm = sqrtf(ss);
    float scale = 1.0f / fmaxf(nrm, NEPS);
    if (tid == 0) g_x2[r] = ss * scale * scale;
#pragma unroll
    for (int i = 0; i < 8; i++) dst[tid + i * 256] = __float2bfloat16(v[i] * scale);
}

// ======================= kernel 2: fused convert + GEMM + f2 =======================
// C[m=batch 256][n=feat 64-slice] = Xn(bf16) . F(fp32->bf16)^T, per branch.
// A double-buffered bf16 via cp.async; B fp32 staged via cp.async then converted
// in-CTA to bf16 (f2 accumulated during conversion).
// grid: (NF/BN, 1, NB), 256 threads (8 warps: 4M x 2N, warp tile 64x32).
__global__ void __launch_bounds__(256, 2) gemm_fused_kernel(
    const float* __restrict__ f0, const float* __restrict__ f1, const float* __restrict__ f2in)
{
    __shared__ __align__(128) __nv_bfloat16 sA[2][BM * BK];   // 2 x 16KB
    __shared__ __align__(128) float         sBf[BN * BK];     // 8KB fp32 staging
    __shared__ __align__(128) __nv_bfloat16 sBc[BN * BK];     // 4KB bf16 converted

    const int tid = threadIdx.x;
    const int wid = tid >> 5;
    const int lid = tid & 31;
    const int br = blockIdx.z;
    const int n0 = blockIdx.x * BN;
    const int warp_m = wid & 3;     // 4 warps in M
    const int warp_n = wid >> 2;    // 2 warps in N

    const __nv_bfloat16* __restrict__ Ab = g_xn + (size_t)(br * BSZ) * DDIM;
    const float* __restrict__ Fb = ((br == 0) ? f0 : (br == 1) ? f1 : f2in) + (size_t)n0 * DDIM;

    const uint32_t sAu  = smem_u32(sA);
    const uint32_t sBfu = smem_u32(sBf);
    const uint32_t sBcu = smem_u32(sBc);

    // --- cp.async mapping for A: 1024 x 16B chunks, 4 per thread ---
    uint32_t soA[4];
    const __nv_bfloat16* gA[4];
#pragma unroll
    for (int i = 0; i < 4; i++) {
        int c = tid + i * 256;
        int row = c >> 2, seg = c & 3;
        soA[i] = (uint32_t)(row * 64 + ((seg ^ ((row >> 1) & 3)) << 4));
        gA[i] = Ab + (size_t)row * DDIM + seg * 8;
    }
    // --- cp.async mapping for B fp32: 512 x 16B chunks, 2 per thread ---
    uint32_t soB[2];
    const float* gB[2];
#pragma unroll
    for (int i = 0; i < 2; i++) {
        int c = tid + i * 256;
        int row = c >> 3, seg = c & 7;
        soB[i] = (uint32_t)(row * 128 + seg * 16);
        gB[i] = Fb + (size_t)row * DDIM + seg * 4;
    }

    // --- conversion mapping: thread -> (feature row, 8-col segment) ---
    const int cr = tid >> 2;        // 0..63 feature row in tile
    const int cq = tid & 3;         // 8-float segment
    const uint32_t cvt_src = sBfu + (uint32_t)(cr * 128 + cq * 32);
    const uint32_t cvt_dst = sBcu + (uint32_t)(cr * 64 + ((cq ^ ((cr >> 1) & 3)) << 4));

    // --- ldmatrix fragment bases ---
    const int rowA = warp_m * 64 + (lid & 15);
    const uint32_t swA = (uint32_t)((rowA >> 1) & 3);
    const int rowB0 = warp_n * 32 + (lid & 15);
    const int rowB1 = rowB0 + 16;
    const uint32_t swB0 = (uint32_t)((rowB0 >> 1) & 3);
    const uint32_t swB1 = (uint32_t)((rowB1 >> 1) & 3);
    const uint32_t hi = (uint32_t)(lid >> 4);

    float acc[4][4][4];
#pragma unroll
    for (int i = 0; i < 4; i++)
#pragma unroll
        for (int j = 0; j < 4; j++)
#pragma unroll
            for (int k = 0; k < 4; k++) acc[i][j][k] = 0.0f;

    float f2acc = 0.0f;

    // prologue: stage 0
#pragma unroll
    for (int i = 0; i < 4; i++) cp16(sAu + soA[i], gA[i]);
#pragma unroll
    for (int i = 0; i < 2; i++) cp16(sBfu + soB[i], gB[i]);
    CP_COMMIT();

    for (int kt = 0; kt < NK; kt++) {
        CP_WAIT0();
        __syncthreads();                          // A(kt&1) + sBf landed; prev ldmatrix done

        // convert fp32 -> bf16, accumulate f2
        {
            float4 u0 = *(const float4*)(uintptr_t)0;  // placeholder avoided: use asm-free loads
            (void)u0;
        }
        {
            const float4 v0 = *reinterpret_cast<const float4*>(sBf + (cvt_src - sBfu) / 4);
            const float4 v1 = *reinterpret_cast<const float4*>(sBf + (cvt_src - sBfu) / 4 + 4);
            f2acc += v0.x * v0.x + v0.y * v0.y + v0.z * v0.z + v0.w * v0.w
                   + v1.x * v1.x + v1.y * v1.y + v1.z * v1.z + v1.w * v1.w;
            __nv_bfloat162 p0 = __floats2bfloat162_rn(v0.x, v0.y);
            __nv_bfloat162 p1 = __floats2bfloat162_rn(v0.z, v0.w);
            __nv_bfloat162 p2 = __floats2bfloat162_rn(v1.x, v1.y);
            __nv_bfloat162 p3 = __floats2bfloat162_rn(v1.z, v1.w);
            sts128u(cvt_dst, *(uint32_t*)&p0, *(uint32_t*)&p1, *(uint32_t*)&p2, *(uint32_t*)&p3);
        }
        __syncthreads();                          // sBc ready; sBf free for refill

        if (kt + 1 < NK) {
            const int koffA = (kt + 1) * BK;      // bf16 elements
            const uint32_t bo = ((kt + 1) & 1) ? (uint32_t)(BM * BK * 2) : 0u;
#pragma unroll
            for (int i = 0; i < 4; i++) cp16(sAu + bo + soA[i], gA[i] + koffA);
#pragma unroll
            for (int i = 0; i < 2; i++) cp16(sBfu + soB[i], gB[i] + koffA);
            CP_COMMIT();
        }

        const uint32_t abase = sAu + ((kt & 1) ? (uint32_t)(BM * BK * 2) : 0u);
#pragma unroll
        for (int ks = 0; ks < 2; ks++) {
            const uint32_t ch = (uint32_t)(ks * 2) + hi;
            uint32_t a[4][4];
#pragma unroll
            for (int mt = 0; mt < 4; mt++)
                ldsm_x4(a[mt], abase + (uint32_t)((rowA + mt * 16) * 64) + ((ch ^ swA) << 4));
            uint32_t b[2][4];
            ldsm_x4(b[0], sBcu + (uint32_t)(rowB0 * 64) + ((ch ^ swB0) << 4));
            ldsm_x4(b[1], sBcu + (uint32_t)(rowB1 * 64) + ((ch ^ swB1) << 4));
#pragma unroll
            for (int mt = 0; mt < 4; mt++)
#pragma unroll
                for (int nt = 0; nt < 4; nt++)
                    mma16816(acc[mt][nt], a[mt], b[nt >> 1][nt & 1], b[nt >> 1][2 + (nt & 1)]);
        }
    }

    // f2 reduce across the 4 threads per feature row
    f2acc += __shfl_down_sync(0xffffffffu, f2acc, 2, 4);
    f2acc += __shfl_down_sync(0xffffffffu, f2acc, 1, 4);
    if ((tid & 3) == 0) g_f2[br * NF + n0 + cr] = f2acc;

    // epilogue: write dot block
    float* Crow = g_dot + (size_t)(br * BSZ + warp_m * 64) * NF + n0 + warp_n * 32;
    const int rr = lid >> 2;
    const int cc = (lid & 3) * 2;
#pragma unroll
    for (int mt = 0; mt < 4; mt++)
#pragma unroll
        for (int nt = 0; nt < 4; nt++) {
            float2 v0 = make_float2(acc[mt][nt][0], acc[mt][nt][1]);
            float2 v1 = make_float2(acc[mt][nt][2], acc[mt][nt][3]);
            *(float2*)&Crow[(size_t)(mt * 16 + rr) * NF + nt * 8 + cc] = v0;
            *(float2*)&Crow[(size_t)(mt * 16 + rr + 8) * NF + nt * 8 + cc] = v1;
        }
}

// ======================= kernel 3: per-row loss =======================
__global__ void __launch_bounds__(256) rowloss_kernel(const int* __restrict__ targets) {
    const int r = blockIdx.x;
    const int br = r >> 8;
    const int b = r & 255;
    const float* drow = g_dot + (size_t)r * NF;
    const float* f2 = g_f2 + br * NF;
    const float x2 = g_x2[r];
    const int tid = threadIdx.x;

    __shared__ float sm[NF];

    float s1 = 0.0f, s2 = 0.0f;
#pragma unroll 4
    for (int i = 0; i < NF / 256; i++) {
        int n = tid + i * 256;
        float dot = drow[n];
        s1 += expf(dot * TEMP_INV);
        float d2 = x2 + f2[n] - 2.0f * dot;
        float d = sqrtf(fmaxf(d2, 0.0f));
        float ed = expf(d);
        s2 += ed;
        sm[n] = ed;
    }
    s1 = blockReduceSum(s1);
    __shared__ float sS1;
    if (tid == 0) sS1 = s1;
    s2 = blockReduceSum(s2);
    __shared__ float sS2;
    if (tid == 0) sS2 = s2;
    __syncthreads();
    const float inv2 = 1.0f / sS2;

    float s3 = 0.0f;
#pragma unroll 4
    for (int i = 0; i < NF / 256; i++) {
        int n = tid + i * 256;
        s3 += expf(sm[n] * inv2);
    }
    s3 = blockReduceSum(s3);

    if (tid == 0) {
        int t = targets[b];
        float dott = drow[t];
        float d2t = x2 + f2[t] - 2.0f * dott;
        float dt = sqrtf(fmaxf(d2t, 0.0f));
        float loss1 = logf(sS1) - dott * TEMP_INV;
        float loss2 = logf(s3) - expf(dt) * inv2;
        g_rowloss[r] = loss1 + loss2;
    }
}

// ======================= kernel 4: final reduce =======================
__global__ void __launch_bounds__(256) final_kernel(float* __restrict__ out) {
    const int tid = threadIdx.x;
    float v = g_rowloss[tid] + g_rowloss[tid + 256] + g_rowloss[tid + 512];
    v = blockReduceSum(v);
    if (tid == 0) out[0] = v * (0.5f / 256.0f);
}

// ======================= launch =======================
extern "C" void kernel_launch(void* const* d_in, const int* in_sizes, int n_in,
                              void* d_out, int out_size) {
    const float* inputs      = (const float*)d_in[0];
    const float* inputs_up   = (const float*)d_in[1];
    const float* inputs_down = (const float*)d_in[2];
    const int*   targets     = (const int*)d_in[3];
    const float* features      = (const float*)d_in[5];
    const float* features_up   = (const float*)d_in[6];
    const float* features_down = (const float*)d_in[7];
    float* out = (float*)d_out;

    prep_x_kernel<<<NB * BSZ, 256>>>(inputs, inputs_up, inputs_down);
    gemm_fused_kernel<<<dim3(NF / BN, 1, NB), 256>>>(features, features_up, features_down);
    rowloss_kernel<<<NB * BSZ, 256>>>(targets);
    final_kernel<<<1, 256>>>(out);
}

// round 4
// speedup vs baseline: 1.3693x; 1.3199x over previous
#include <cuda_runtime.h>
#include <cuda_bf16.h>
#include <cstdint>

// ======================= problem constants =======================
#define NB   3
#define BSZ  256
#define NF   8192
#define DDIM 2048
#define TEMP_INV 20.0f
#define NEPS 1e-12f

// GEMM tiling
#define BM 256
#define BN 64
#define BK 64
#define NK (DDIM / BK)          // 32
#define A_STAGE_BYTES (BM * BK * 2)   // 32768
#define B_STAGE_BYTES (BN * BK * 2)   // 8192
#define SMEM_DYN (3 * A_STAGE_BYTES + 2 * B_STAGE_BYTES)  // 114688

// ======================= static device scratch =======================
__device__ __align__(256) __nv_bfloat16 g_xn[NB * BSZ * DDIM];
__device__ float g_x2[NB * BSZ];
__device__ float g_f2[NB * NF];
__device__ __align__(256) float g_dot[(size_t)NB * BSZ * NF];
__device__ float g_rowloss[NB * BSZ];

// ======================= helpers =======================
__device__ __forceinline__ uint32_t smem_u32(const void* p) {
    uint32_t a;
    asm("{ .reg .u64 t; cvta.to.shared.u64 t, %1; cvt.u32.u64 %0, t; }" : "=r"(a) : "l"(p));
    return a;
}

__device__ __forceinline__ void cp16(uint32_t saddr, const void* g) {
    asm volatile("cp.async.cg.shared.global [%0], [%1], 16;" :: "r"(saddr), "l"(g) : "memory");
}
#define CP_COMMIT() asm volatile("cp.async.commit_group;" ::: "memory")
#define CP_WAIT0()  asm volatile("cp.async.wait_group 0;" ::: "memory")
#define CP_WAIT1()  asm volatile("cp.async.wait_group 1;" ::: "memory")

__device__ __forceinline__ void ldsm_x4(uint32_t* r, uint32_t addr) {
    asm volatile("ldmatrix.sync.aligned.m8n8.x4.shared.b16 {%0,%1,%2,%3}, [%4];"
                 : "=r"(r[0]), "=r"(r[1]), "=r"(r[2]), "=r"(r[3]) : "r"(addr));
}

__device__ __forceinline__ void mma16816(float* c, const uint32_t* a, uint32_t b0, uint32_t b1) {
    asm volatile(
        "mma.sync.aligned.m16n8k16.row.col.f32.bf16.bf16.f32 "
        "{%0,%1,%2,%3}, {%4,%5,%6,%7}, {%8,%9}, {%0,%1,%2,%3};"
        : "+f"(c[0]), "+f"(c[1]), "+f"(c[2]), "+f"(c[3])
        : "r"(a[0]), "r"(a[1]), "r"(a[2]), "r"(a[3]), "r"(b0), "r"(b1));
}

__device__ __forceinline__ void sts128u(uint32_t addr, uint32_t x, uint32_t y, uint32_t z, uint32_t w) {
    asm volatile("st.shared.v4.b32 [%0], {%1, %2, %3, %4};"
                 :: "r"(addr), "r"(x), "r"(y), "r"(z), "r"(w) : "memory");
}

__device__ __forceinline__ float blockReduceSum(float v) {
    __shared__ float red[8];
    const unsigned m = 0xffffffffu;
    v += __shfl_xor_sync(m, v, 16);
    v += __shfl_xor_sync(m, v, 8);
    v += __shfl_xor_sync(m, v, 4);
    v += __shfl_xor_sync(m, v, 2);
    v += __shfl_xor_sync(m, v, 1);
    __syncthreads();
    if ((threadIdx.x & 31) == 0) red[threadIdx.x >> 5] = v;
    __syncthreads();
    if (threadIdx.x < 8) {
        v = red[threadIdx.x];
        v += __shfl_xor_sync(0xffu, v, 4);
        v += __shfl_xor_sync(0xffu, v, 2);
        v += __shfl_xor_sync(0xffu, v, 1);
    }
    return v;
}

// ======================= kernel 1: normalize x rows -> bf16 =======================
__global__ void __launch_bounds__(256) prep_x_kernel(
    const float* __restrict__ x0, const float* __restrict__ x1, const float* __restrict__ x2)
{
    const int r = blockIdx.x;
    const int tid = threadIdx.x;
    const int br = r >> 8;
    const int b = r & 255;
    const float* base = (br == 0) ? x0 : (br == 1) ? x1 : x2;
    const float* src = base + (size_t)b * DDIM;
    __nv_bfloat16* dst = g_xn + (size_t)r * DDIM;

    float v[8];
    float ss = 0.0f;
#pragma unroll
    for (int i = 0; i < 8; i++) {
        v[i] = src[tid + i * 256];
        ss += v[i] * v[i];
    }
    ss = blockReduceSum(ss);
    __shared__ float s_bcast;
    if (tid == 0) s_bcast = ss;
    __syncthreads();
    ss = s_bcast;

    float nrm = sqrtf(ss);
    float scale = 1.0f / fmaxf(nrm, NEPS);
    if (tid == 0) g_x2[r] = ss * scale * scale;
#pragma unroll
    for (int i = 0; i < 8; i++) dst[tid + i * 256] = __float2bfloat16(v[i] * scale);
}

// ======================= kernel 2: fused convert + GEMM + f2 =======================
// BM=256 (whole batch) x BN=64 x BK=64. 3-stage cp.async for A; B converted
// fp32->bf16 in registers one iteration ahead into double-buffered sBc.
// grid: (NF/BN, 1, NB); 256 threads = 8 warps (4M x 2N, warp tile 64x32).
__global__ void __launch_bounds__(256, 2) gemm_fused_kernel(
    const float* __restrict__ f0, const float* __restrict__ f1, const float* __restrict__ f2in)
{
    extern __shared__ __align__(128) char dyn[];
    const uint32_t sAu  = smem_u32(dyn);                         // 3 x 32KB
    const uint32_t sBcu = sAu + 3 * A_STAGE_BYTES;               // 2 x 8KB

    const int tid = threadIdx.x;
    const int wid = tid >> 5;
    const int lid = tid & 31;
    const int br = blockIdx.z;
    const int n0 = blockIdx.x * BN;
    const int warp_m = wid & 3;
    const int warp_n = wid >> 2;

    const __nv_bfloat16* __restrict__ Ab = g_xn + (size_t)(br * BSZ) * DDIM;
    const float* __restrict__ Fb = ((br == 0) ? f0 : (br == 1) ? f1 : f2in) + (size_t)n0 * DDIM;

    // --- A cp.async mapping: 2048 chunks (16B), 8 per thread ---
    const int arow = tid >> 3;          // 0..31
    const int aseg = tid & 7;
    const uint32_t soA = (uint32_t)(arow * 128 + ((aseg ^ (arow & 7)) << 4));
    const __nv_bfloat16* gA = Ab + (size_t)arow * DDIM + aseg * 8;

    // --- B mapping: thread owns rows (tid>>3) and (tid>>3)+32, seg tid&7 (8 fp32) ---
    const int brow = tid >> 3;
    const int bseg = tid & 7;
    const float* gB0 = Fb + (size_t)brow * DDIM + bseg * 8;
    const float* gB1 = gB0 + (size_t)32 * DDIM;
    const uint32_t dstB = (uint32_t)(brow * 128 + ((bseg ^ (brow & 7)) << 4)); // +32*128 for row+32

    // --- ldmatrix fragment bases ---
    const int rowA = warp_m * 64 + (lid & 15);
    const uint32_t xA = (uint32_t)(rowA & 7);
    const int rowB0 = warp_n * 32 + (lid & 15);
    const int rowB1 = rowB0 + 16;
    const uint32_t xB0 = (uint32_t)(rowB0 & 7);
    const uint32_t xB1 = (uint32_t)(rowB1 & 7);
    const uint32_t hi = (uint32_t)(lid >> 4);

    float acc[4][4][4];
#pragma unroll
    for (int i = 0; i < 4; i++)
#pragma unroll
        for (int j = 0; j < 4; j++)
#pragma unroll
            for (int k = 0; k < 4; k++) acc[i][j][k] = 0.0f;

    float f2a = 0.0f, f2b = 0.0f;
    float4 v0, v1, v2, v3;

    // ---------- prologue ----------
    // commit A stage 0 and 1
#pragma unroll
    for (int i = 0; i < 8; i++) cp16(sAu + soA + i * 4096, gA + (size_t)(32 * i) * DDIM);
    CP_COMMIT();
#pragma unroll
    for (int i = 0; i < 8; i++)
        cp16(sAu + A_STAGE_BYTES + soA + i * 4096, gA + (size_t)(32 * i) * DDIM + BK);
    CP_COMMIT();
    // B(0) into regs
    v0 = *(const float4*)(gB0);
    v1 = *(const float4*)(gB0 + 4);
    v2 = *(const float4*)(gB1);
    v3 = *(const float4*)(gB1 + 4);
    CP_WAIT1();   // A stage 0 landed
    // convert B(0) -> sBc[0], accumulate f2
    {
        f2a += v0.x*v0.x + v0.y*v0.y + v0.z*v0.z + v0.w*v0.w
             + v1.x*v1.x + v1.y*v1.y + v1.z*v1.z + v1.w*v1.w;
        f2b += v2.x*v2.x + v2.y*v2.y + v2.z*v2.z + v2.w*v2.w
             + v3.x*v3.x + v3.y*v3.y + v3.z*v3.z + v3.w*v3.w;
        __nv_bfloat162 p0 = __floats2bfloat162_rn(v0.x, v0.y);
        __nv_bfloat162 p1 = __floats2bfloat162_rn(v0.z, v0.w);
        __nv_bfloat162 p2 = __floats2bfloat162_rn(v1.x, v1.y);
        __nv_bfloat162 p3 = __floats2bfloat162_rn(v1.z, v1.w);
        sts128u(sBcu + dstB, *(uint32_t*)&p0, *(uint32_t*)&p1, *(uint32_t*)&p2, *(uint32_t*)&p3);
        p0 = __floats2bfloat162_rn(v2.x, v2.y);
        p1 = __floats2bfloat162_rn(v2.z, v2.w);
        p2 = __floats2bfloat162_rn(v3.x, v3.y);
        p3 = __floats2bfloat162_rn(v3.z, v3.w);
        sts128u(sBcu + dstB + 32 * 128, *(uint32_t*)&p0, *(uint32_t*)&p1, *(uint32_t*)&p2, *(uint32_t*)&p3);
    }
    // B(1) into regs
    v0 = *(const float4*)(gB0 + BK);
    v1 = *(const float4*)(gB0 + BK + 4);
    v2 = *(const float4*)(gB1 + BK);
    v3 = *(const float4*)(gB1 + BK + 4);
    __syncthreads();

    // ---------- mainloop ----------
    int stage = 0;   // A stage index of kt
    for (int kt = 0; kt < NK; kt++) {
        // commit A(kt+2) into stage (kt+2)%3  (that stage was last read at kt-1)
        if (kt + 2 < NK) {
            const int s2 = (stage >= 1) ? stage - 1 : stage + 2;   // (kt+2)%3
            const size_t ko = (size_t)(kt + 2) * BK;
#pragma unroll
            for (int i = 0; i < 8; i++)
                cp16(sAu + (uint32_t)s2 * A_STAGE_BYTES + soA + i * 4096,
                     gA + (size_t)(32 * i) * DDIM + ko);
            CP_COMMIT();
        }

        // MMA over current buffers
        const uint32_t abase = sAu + (uint32_t)stage * A_STAGE_BYTES;
        const uint32_t bbase = sBcu + (uint32_t)(kt & 1) * B_STAGE_BYTES;
#pragma unroll
        for (int ks = 0; ks < 4; ks++) {
            const uint32_t ch = (uint32_t)(ks * 2) + hi;
            uint32_t a[4][4];
#pragma unroll
            for (int mt = 0; mt < 4; mt++)
                ldsm_x4(a[mt], abase + (uint32_t)((rowA + mt * 16) * 128) + ((ch ^ xA) << 4));
            uint32_t b[2][4];
            ldsm_x4(b[0], bbase + (uint32_t)(rowB0 * 128) + ((ch ^ xB0) << 4));
            ldsm_x4(b[1], bbase + (uint32_t)(rowB1 * 128) + ((ch ^ xB1) << 4));
#pragma unroll
            for (int mt = 0; mt < 4; mt++)
#pragma unroll
                for (int nt = 0; nt < 4; nt++)
                    mma16816(acc[mt][nt], a[mt], b[nt >> 1][nt & 1], b[nt >> 1][2 + (nt & 1)]);
        }

        if (kt + 1 < NK) {
            // wait for A stage (kt+1)%3
            if (kt + 2 < NK) { CP_WAIT1(); } else { CP_WAIT0(); }
            // convert B(kt+1) regs -> sBc[(kt+1)&1]
            {
                f2a += v0.x*v0.x + v0.y*v0.y + v0.z*v0.z + v0.w*v0.w
                     + v1.x*v1.x + v1.y*v1.y + v1.z*v1.z + v1.w*v1.w;
                f2b += v2.x*v2.x + v2.y*v2.y + v2.z*v2.z + v2.w*v2.w
                     + v3.x*v3.x + v3.y*v3.y + v3.z*v3.z + v3.w*v3.w;
                const uint32_t bb = sBcu + (uint32_t)((kt + 1) & 1) * B_STAGE_BYTES;
                __nv_bfloat162 p0 = __floats2bfloat162_rn(v0.x, v0.y);
                __nv_bfloat162 p1 = __floats2bfloat162_rn(v0.z, v0.w);
                __nv_bfloat162 p2 = __floats2bfloat162_rn(v1.x, v1.y);
                __nv_bfloat162 p3 = __floats2bfloat162_rn(v1.z, v1.w);
                sts128u(bb + dstB, *(uint32_t*)&p0, *(uint32_t*)&p1, *(uint32_t*)&p2, *(uint32_t*)&p3);
                p0 = __floats2bfloat162_rn(v2.x, v2.y);
                p1 = __floats2bfloat162_rn(v2.z, v2.w);
                p2 = __floats2bfloat162_rn(v3.x, v3.y);
                p3 = __floats2bfloat162_rn(v3.z, v3.w);
                sts128u(bb + dstB + 32 * 128, *(uint32_t*)&p0, *(uint32_t*)&p1, *(uint32_t*)&p2, *(uint32_t*)&p3);
            }
            // load B(kt+2) into regs
            if (kt + 2 < NK) {
                const size_t ko = (size_t)(kt + 2) * BK;
                v0 = *(const float4*)(gB0 + ko);
                v1 = *(const float4*)(gB0 + ko + 4);
                v2 = *(const float4*)(gB1 + ko);
                v3 = *(const float4*)(gB1 + ko + 4);
            }
            __syncthreads();
        }
        stage = (stage >= 2) ? 0 : stage + 1;
    }

    // f2 reduce across the 8 seg-lanes per feature row
    f2a += __shfl_down_sync(0xffffffffu, f2a, 4, 8);
    f2a += __shfl_down_sync(0xffffffffu, f2a, 2, 8);
    f2a += __shfl_down_sync(0xffffffffu, f2a, 1, 8);
    f2b += __shfl_down_sync(0xffffffffu, f2b, 4, 8);
    f2b += __shfl_down_sync(0xffffffffu, f2b, 2, 8);
    f2b += __shfl_down_sync(0xffffffffu, f2b, 1, 8);
    if (bseg == 0) {
        g_f2[br * NF + n0 + brow] = f2a;
        g_f2[br * NF + n0 + brow + 32] = f2b;
    }

    // epilogue: write dot block
    float* Crow = g_dot + (size_t)(br * BSZ + warp_m * 64) * NF + n0 + warp_n * 32;
    const int rr = lid >> 2;
    const int cc = (lid & 3) * 2;
#pragma unroll
    for (int mt = 0; mt < 4; mt++)
#pragma unroll
        for (int nt = 0; nt < 4; nt++) {
            float2 w0 = make_float2(acc[mt][nt][0], acc[mt][nt][1]);
            float2 w1 = make_float2(acc[mt][nt][2], acc[mt][nt][3]);
            *(float2*)&Crow[(size_t)(mt * 16 + rr) * NF + nt * 8 + cc] = w0;
            *(float2*)&Crow[(size_t)(mt * 16 + rr + 8) * NF + nt * 8 + cc] = w1;
        }
}

// ======================= kernel 3: per-row loss =======================
__global__ void __launch_bounds__(256) rowloss_kernel(const int* __restrict__ targets) {
    const int r = blockIdx.x;
    const int br = r >> 8;
    const int b = r & 255;
    const float* drow = g_dot + (size_t)r * NF;
    const float* f2 = g_f2 + br * NF;
    const float x2 = g_x2[r];
    const int tid = threadIdx.x;

    __shared__ float sm[NF];

    float s1 = 0.0f, s2 = 0.0f;
#pragma unroll 4
    for (int i = 0; i < NF / 256; i++) {
        int n = tid + i * 256;
        float dot = drow[n];
        s1 += expf(dot * TEMP_INV);
        float d2 = x2 + f2[n] - 2.0f * dot;
        float d = sqrtf(fmaxf(d2, 0.0f));
        float ed = expf(d);
        s2 += ed;
        sm[n] = ed;
    }
    s1 = blockReduceSum(s1);
    __shared__ float sS1;
    if (tid == 0) sS1 = s1;
    s2 = blockReduceSum(s2);
    __shared__ float sS2;
    if (tid == 0) sS2 = s2;
    __syncthreads();
    const float inv2 = 1.0f / sS2;

    float s3 = 0.0f;
#pragma unroll 4
    for (int i = 0; i < NF / 256; i++) {
        int n = tid + i * 256;
        s3 += expf(sm[n] * inv2);
    }
    s3 = blockReduceSum(s3);

    if (tid == 0) {
        int t = targets[b];
        float dott = drow[t];
        float d2t = x2 + f2[t] - 2.0f * dott;
        float dt = sqrtf(fmaxf(d2t, 0.0f));
        float loss1 = logf(sS1) - dott * TEMP_INV;
        float loss2 = logf(s3) - expf(dt) * inv2;
        g_rowloss[r] = loss1 + loss2;
    }
}

// ======================= kernel 4: final reduce =======================
__global__ void __launch_bounds__(256) final_kernel(float* __restrict__ out) {
    const int tid = threadIdx.x;
    float v = g_rowloss[tid] + g_rowloss[tid + 256] + g_rowloss[tid + 512];
    v = blockReduceSum(v);
    if (tid == 0) out[0] = v * (0.5f / 256.0f);
}

// ======================= launch =======================
extern "C" void kernel_launch(void* const* d_in, const int* in_sizes, int n_in,
                              void* d_out, int out_size) {
    const float* inputs      = (const float*)d_in[0];
    const float* inputs_up   = (const float*)d_in[1];
    const float* inputs_down = (const float*)d_in[2];
    const int*   targets     = (const int*)d_in[3];
    const float* features      = (const float*)d_in[5];
    const float* features_up   = (const float*)d_in[6];
    const float* features_down = (const float*)d_in[7];
    float* out = (float*)d_out;

    cudaFuncSetAttribute(gemm_fused_kernel,
                         cudaFuncAttributeMaxDynamicSharedMemorySize, SMEM_DYN);

    prep_x_kernel<<<NB * BSZ, 256>>>(inputs, inputs_up, inputs_down);
    gemm_fused_kernel<<<dim3(NF / BN, 1, NB), 256, SMEM_DYN>>>(features, features_up, features_down);
    rowloss_kernel<<<NB * BSZ, 256>>>(targets);
    final_kernel<<<1, 256>>>(out);
}